// round 1
// baseline (speedup 1.0000x reference)
#include <cuda_runtime.h>

// ---------------------------------------------------------------------------
// CentralCritic: fused leave-one-out critic evaluation.
//   enc = relu(state @ enc_W + enc_b)                       [B,128]
//   for each of 20 (agent i, head j) pairs:
//     x   = [acs[k!=i, head] (48) ; enc (128)]              [B,176]
//     h   = relu(x @ W1 + b1)                               [B,128]
//     c   = argmax_c acs[i, head, b, :]
//     out = h . W2[:,c] + b2[c]                             [B]
// Output layout: extr (A*H*B) then intr (A*HI*B).
// ---------------------------------------------------------------------------

#define A_  4
#define H_  3
#define HI_ 2
#define C_  16
#define S_  256
#define D_  128
#define IN_ 176
#define BT  64      // batch rows per CTA
#define KT  16      // K chunk

// scratch for enc (B=32768 max)
__device__ float g_enc[32768 * 128];

__constant__ int c_loo[4][3] = {{1,2,3},{0,2,3},{0,1,3},{0,1,2}};

// ------------------------- encoder GEMM -----------------------------------
__global__ __launch_bounds__(256) void enc_kernel(
    const float* __restrict__ state, const float* __restrict__ W,
    const float* __restrict__ b, int B)
{
    __shared__ float Xs[KT][BT + 1];
    __shared__ float Ws[KT][D_];

    const int row0 = blockIdx.x * BT;
    const int tid  = threadIdx.x;
    const int tn = tid & 15, tm = tid >> 4;
    const int m0 = tm * 4, n0 = tn * 8;

    float acc[4][8];
#pragma unroll
    for (int m = 0; m < 4; m++)
#pragma unroll
        for (int n = 0; n < 8; n++) acc[m][n] = 0.f;

    for (int kk = 0; kk < S_; kk += KT) {
#pragma unroll
        for (int it = 0; it < 4; it++) {
            int e = tid + it * 256;
            int m = e >> 4, k = e & 15;
            Xs[k][m] = state[(size_t)(row0 + m) * S_ + kk + k];
        }
#pragma unroll
        for (int it = 0; it < 8; it++) {
            int e = tid + it * 256;
            int n = e & 127, k = e >> 7;
            Ws[k][n] = W[(size_t)(kk + k) * D_ + n];
        }
        __syncthreads();
#pragma unroll
        for (int k = 0; k < KT; k++) {
            float xr[4], wr[8];
#pragma unroll
            for (int m = 0; m < 4; m++) xr[m] = Xs[k][m0 + m];
#pragma unroll
            for (int n = 0; n < 8; n++) wr[n] = Ws[k][n0 + n];
#pragma unroll
            for (int m = 0; m < 4; m++)
#pragma unroll
                for (int n = 0; n < 8; n++) acc[m][n] += xr[m] * wr[n];
        }
        __syncthreads();
    }

#pragma unroll
    for (int m = 0; m < 4; m++) {
        int row = row0 + m0 + m;
#pragma unroll
        for (int n = 0; n < 8; n++) {
            float v = acc[m][n] + b[n0 + n];
            g_enc[(size_t)row * D_ + n0 + n] = fmaxf(v, 0.f);
        }
    }
}

// ------------------------- critic (fused layer1 + gathered layer2) ---------
struct GemmSmem { float Xs[KT][BT + 1]; float Ws[KT][D_]; };
struct HSmem    { float Hs[BT][D_ + 4]; };
union  SmemU    { GemmSmem g; HSmem h; };

__global__ __launch_bounds__(256) void critic_kernel(
    const float* __restrict__ acs,
    const float* __restrict__ eW1, const float* __restrict__ eb1,
    const float* __restrict__ eW2, const float* __restrict__ eb2,
    const float* __restrict__ iW1, const float* __restrict__ ib1,
    const float* __restrict__ iW2, const float* __restrict__ ib2,
    float* __restrict__ out, int B)
{
    __shared__ SmemU sm;
    __shared__ float W2s[D_][C_];
    __shared__ float b2s[C_];

    const int p    = blockIdx.y;
    const int row0 = blockIdx.x * BT;
    const int tid  = threadIdx.x;

    int i, j, head;
    const float *W1, *b1, *W2, *b2;
    float* outp;
    if (p < A_ * H_) {
        i = p / H_; j = p % H_; head = j;
        W1 = eW1 + (size_t)(j * A_ + i) * IN_ * D_;
        b1 = eb1 + (size_t)(j * A_ + i) * D_;
        W2 = eW2 + (size_t)(j * A_ + i) * D_ * C_;
        b2 = eb2 + (size_t)(j * A_ + i) * C_;
        outp = out + (size_t)(i * H_ + j) * B;
    } else {
        int q = p - A_ * H_;
        i = q / HI_; j = q % HI_; head = j + 1;
        W1 = iW1 + (size_t)(j * A_ + i) * IN_ * D_;
        b1 = ib1 + (size_t)(j * A_ + i) * D_;
        W2 = iW2 + (size_t)(j * A_ + i) * D_ * C_;
        b2 = ib2 + (size_t)(j * A_ + i) * C_;
        outp = out + (size_t)A_ * H_ * B + (size_t)(i * HI_ + j) * B;
    }

    const float* acsA[3];
    acsA[0] = acs + (size_t)(c_loo[i][0] * H_ + head) * B * C_;
    acsA[1] = acs + (size_t)(c_loo[i][1] * H_ + head) * B * C_;
    acsA[2] = acs + (size_t)(c_loo[i][2] * H_ + head) * B * C_;

    const int tn = tid & 15, tm = tid >> 4;
    const int m0 = tm * 4, n0 = tn * 8;

    float acc[4][8];
#pragma unroll
    for (int m = 0; m < 4; m++)
#pragma unroll
        for (int n = 0; n < 8; n++) acc[m][n] = 0.f;

    // ----- layer 1: [BT,176] @ [176,128] -----
    for (int kc = 0; kc < IN_ / KT; kc++) {   // 11 chunks of 16
        const int kbase = kc * KT;
#pragma unroll
        for (int it = 0; it < 4; it++) {
            int e = tid + it * 256;
            int m = e >> 4, k = e & 15;
            int row = row0 + m;
            float v;
            if (kbase < 48) {
                // whole chunk comes from one leave-one-out agent block
                const float* ap = acsA[kbase >> 4];
                v = ap[(size_t)row * C_ + k];
            } else {
                v = g_enc[(size_t)row * D_ + (kbase - 48) + k];
            }
            sm.g.Xs[k][m] = v;
        }
#pragma unroll
        for (int it = 0; it < 8; it++) {
            int e = tid + it * 256;
            int n = e & 127, k = e >> 7;
            sm.g.Ws[k][n] = W1[(size_t)(kbase + k) * D_ + n];
        }
        __syncthreads();
#pragma unroll
        for (int k = 0; k < KT; k++) {
            float xr[4], wr[8];
#pragma unroll
            for (int m = 0; m < 4; m++) xr[m] = sm.g.Xs[k][m0 + m];
#pragma unroll
            for (int n = 0; n < 8; n++) wr[n] = sm.g.Ws[k][n0 + n];
#pragma unroll
            for (int m = 0; m < 4; m++)
#pragma unroll
                for (int n = 0; n < 8; n++) acc[m][n] += xr[m] * wr[n];
        }
        __syncthreads();
    }

    // ----- bias + relu into Hs; stage W2/b2 concurrently -----
#pragma unroll
    for (int m = 0; m < 4; m++)
#pragma unroll
        for (int n = 0; n < 8; n++)
            sm.h.Hs[m0 + m][n0 + n] = fmaxf(acc[m][n] + b1[n0 + n], 0.f);

    for (int e = tid; e < D_ * C_; e += 256)
        W2s[e >> 4][e & 15] = W2[e];
    if (tid < C_) b2s[tid] = b2[tid];
    __syncthreads();

    // ----- layer 2: gathered column only -----
    if (tid < BT) {
        int row = row0 + tid;
        const float* ar = acs + ((size_t)(i * H_ + head) * B + row) * C_;
        float best = ar[0]; int c = 0;
#pragma unroll
        for (int cc = 1; cc < C_; cc++) {
            float v = ar[cc];
            if (v > best) { best = v; c = cc; }
        }
        float q = b2s[c];
#pragma unroll
        for (int d = 0; d < D_; d++) q += sm.h.Hs[tid][d] * W2s[d][c];
        outp[row] = q;
    }
}

// ---------------------------------------------------------------------------
extern "C" void kernel_launch(void* const* d_in, const int* in_sizes, int n_in,
                              void* d_out, int out_size)
{
    const float* state = (const float*)d_in[0];
    const float* acs   = (const float*)d_in[1];
    const float* encW  = (const float*)d_in[2];
    const float* encb  = (const float*)d_in[3];
    const float* eW1   = (const float*)d_in[4];
    const float* eb1   = (const float*)d_in[5];
    const float* eW2   = (const float*)d_in[6];
    const float* eb2   = (const float*)d_in[7];
    const float* iW1   = (const float*)d_in[8];
    const float* ib1   = (const float*)d_in[9];
    const float* iW2   = (const float*)d_in[10];
    const float* ib2   = (const float*)d_in[11];
    float* out = (float*)d_out;

    const int B = in_sizes[0] / S_;   // 32768

    enc_kernel<<<B / BT, 256>>>(state, encW, encb, B);

    dim3 grid(B / BT, A_ * H_ + A_ * HI_);   // (512, 20)
    critic_kernel<<<grid, 256>>>(acs, eW1, eb1, eW2, eb2,
                                 iW1, ib1, iW2, ib2, out, B);
}

// round 3
// speedup vs baseline: 4.4249x; 4.4249x over previous
#include <cuda_runtime.h>
#include <cstdint>

// ---------------------------------------------------------------------------
// CentralCritic via warp-level tf32 mma.sync (sm_80-compatible PTX — the
// harness build path targets plain sm_103, so tcgen05/'a' features are out).
//   enc:    relu(state[B,256] @ encW[256,128] + b) -> g_enc
//   critic: per pair p (20): h = relu([acs_loo(48)|enc(128)] @ W1 + b1)
//           out = h . W2[:, argmax(acs_self)] + b2[c]
// ---------------------------------------------------------------------------

#define A_   4
#define H_   3
#define HI_  2
#define C_   16
#define S_   256
#define D_   128
#define IN_  176
#define NPAIR 20
#define NT    4      // 128-row tiles per critic CTA
#define NTE   4      // 64-row tiles per enc CTA

// smem strides (floats), chosen for conflict-free fragment loads
#define XS_ST  180   // critic X rows (176 + pad): bank = 20g+t, all distinct
#define WS_ST  136   // W rows (128 + pad): bank = 8t+g, all distinct
#define XE_ST  260   // enc X rows (256 + pad): bank = 4g+t, all distinct

// critic smem offsets (in floats)
#define WS_OFF   0                       // 176*136 = 23936
#define XS_OFF   23936                   // 128*180 = 23040
#define W2_OFF   46976                   // 128*17  = 2176
#define B1_OFF   49152                   // 128
#define B2_OFF   49280                   // 16
#define PART_OFF 49296                   // 128
#define CIDX_OFF 49424                   // 128 (ints)
#define K_SMEMB  (49552 * 4)

// enc smem offsets (floats)
#define WSE_OFF  0                       // 256*136 = 34816
#define XSE_OFF  34816                   // 64*260  = 16640
#define BE_OFF   51456                   // 128
#define E_SMEMB  (51584 * 4)

__device__ float g_enc[32768 * D_];

__constant__ int c_loo[4][3] = {{1,2,3},{0,2,3},{0,1,3},{0,1,2}};

// ---- helpers ---------------------------------------------------------------
__device__ __forceinline__ uint32_t smem_u32(const void* p) {
    uint32_t r;
    asm("{ .reg .u64 t; cvta.to.shared.u64 t, %1; cvt.u32.u64 %0, t; }"
        : "=r"(r) : "l"(p));
    return r;
}
__device__ __forceinline__ uint32_t tf32r(float x) {
    uint32_t y; asm("cvt.rna.tf32.f32 %0, %1;" : "=r"(y) : "f"(x)); return y;
}
__device__ __forceinline__ void cpasync16(uint32_t dst, const void* src) {
    asm volatile("cp.async.cg.shared.global [%0], [%1], 16;"
                 :: "r"(dst), "l"(src));
}
#define CPCOMMIT() asm volatile("cp.async.commit_group;" ::: "memory")
#define CPWAIT0()  asm volatile("cp.async.wait_group 0;" ::: "memory")

__device__ __forceinline__ void mma8(float* d, const uint32_t* a,
                                     const uint32_t* b) {
    asm volatile(
        "mma.sync.aligned.m16n8k8.row.col.f32.tf32.tf32.f32 "
        "{%0,%1,%2,%3}, {%4,%5,%6,%7}, {%8,%9}, {%0,%1,%2,%3};"
        : "+f"(d[0]), "+f"(d[1]), "+f"(d[2]), "+f"(d[3])
        : "r"(a[0]), "r"(a[1]), "r"(a[2]), "r"(a[3]), "r"(b[0]), "r"(b[1]));
}

// ---------------------------------------------------------------------------
// encoder: [B,256] @ [256,128] + bias, relu -> g_enc.  M-tile = 64.
// warps: wm = wid>>2 (2), wn = wid&3 (4); warp tile 32x32.
// ---------------------------------------------------------------------------
__global__ __launch_bounds__(256, 1) void enc_kernel(
    const float* __restrict__ state, const float* __restrict__ encW,
    const float* __restrict__ encb, int B)
{
    extern __shared__ float smf[];
    const int tid = threadIdx.x, wid = tid >> 5, lane = tid & 31;
    const int g = lane >> 2, t = lane & 3;
    const int wm = wid >> 2, wn = wid & 3;
    const int wr = wm * 32, wc = wn * 32;

    // stage Wenc (cvt.rna) : 256x128 -> [k][n] stride 136
    for (int it = 0; it < 32; it++) {
        int fi = it * 256 + tid;            // float4 index, 8192 total
        int k = fi >> 5, n4 = fi & 31;
        float4 v = *(const float4*)(encW + (size_t)k * D_ + n4 * 4);
        uint4 w; w.x = tf32r(v.x); w.y = tf32r(v.y);
        w.z = tf32r(v.z); w.w = tf32r(v.w);
        *(uint4*)(smf + WSE_OFF + k * WS_ST + n4 * 4) = w;
    }
    if (tid < D_) smf[BE_OFF + tid] = encb[tid];

    const uint32_t xbase = smem_u32(smf + XSE_OFF);
    const int tile0 = blockIdx.x * NTE;

    // prologue: stage tile 0 (64 rows x 64 chunks of 16B)
    {
        int row0 = tile0 * 64;
        for (int it = 0; it < 16; it++) {
            int idx = it * 256 + tid;
            int c = idx & 63, row = idx >> 6;
            cpasync16(xbase + (uint32_t)(row * XE_ST + c * 4) * 4,
                      state + (size_t)(row0 + row) * S_ + c * 4);
        }
        CPCOMMIT();
    }
    CPWAIT0();
    __syncthreads();

    for (int tt = 0; tt < NTE; tt++) {
        const int row0 = (tile0 + tt) * 64;
        float acc[2][4][4];
#pragma unroll
        for (int mi = 0; mi < 2; mi++)
#pragma unroll
            for (int ni = 0; ni < 4; ni++)
#pragma unroll
                for (int e = 0; e < 4; e++) acc[mi][ni][e] = 0.f;

        const uint32_t* Xu = (const uint32_t*)(smf + XSE_OFF);
        const uint32_t* Wu = (const uint32_t*)(smf + WSE_OFF);
#pragma unroll
        for (int ks = 0; ks < 32; ks++) {
            const int k0 = ks * 8;
            uint32_t a[2][4], b[4][2];
#pragma unroll
            for (int mi = 0; mi < 2; mi++) {
                int r = wr + mi * 16 + g;
                a[mi][0] = Xu[r * XE_ST + k0 + t];
                a[mi][1] = Xu[(r + 8) * XE_ST + k0 + t];
                a[mi][2] = Xu[r * XE_ST + k0 + t + 4];
                a[mi][3] = Xu[(r + 8) * XE_ST + k0 + t + 4];
            }
#pragma unroll
            for (int ni = 0; ni < 4; ni++) {
                int n = wc + ni * 8 + g;
                b[ni][0] = Wu[(k0 + t) * WS_ST + n];
                b[ni][1] = Wu[(k0 + t + 4) * WS_ST + n];
            }
#pragma unroll
            for (int mi = 0; mi < 2; mi++)
#pragma unroll
                for (int ni = 0; ni < 4; ni++)
                    mma8(acc[mi][ni], a[mi], b[ni]);
        }
        __syncthreads();   // all warps done reading Xs

        if (tt + 1 < NTE) {
            int nrow0 = (tile0 + tt + 1) * 64;
            for (int it = 0; it < 16; it++) {
                int idx = it * 256 + tid;
                int c = idx & 63, row = idx >> 6;
                cpasync16(xbase + (uint32_t)(row * XE_ST + c * 4) * 4,
                          state + (size_t)(nrow0 + row) * S_ + c * 4);
            }
            CPCOMMIT();
        }

        // epilogue: bias + relu, store to g_enc
#pragma unroll
        for (int mi = 0; mi < 2; mi++) {
            int r0 = row0 + wr + mi * 16 + g;
#pragma unroll
            for (int ni = 0; ni < 4; ni++) {
                int col = wc + ni * 8 + 2 * t;
                float b0 = smf[BE_OFF + col], b1v = smf[BE_OFF + col + 1];
                float2 o0, o1;
                o0.x = fmaxf(acc[mi][ni][0] + b0, 0.f);
                o0.y = fmaxf(acc[mi][ni][1] + b1v, 0.f);
                o1.x = fmaxf(acc[mi][ni][2] + b0, 0.f);
                o1.y = fmaxf(acc[mi][ni][3] + b1v, 0.f);
                *(float2*)(g_enc + (size_t)r0 * D_ + col) = o0;
                *(float2*)(g_enc + (size_t)(r0 + 8) * D_ + col) = o1;
            }
        }

        if (tt + 1 < NTE) CPWAIT0();
        __syncthreads();
    }
}

// ---------------------------------------------------------------------------
// critic: per pair p: h = relu(X @ W1 + b1), out = h . W2[:,c] + b2[c].
// warps: wm = wid>>1 (4), wn = wid&1 (2); warp tile 32x64.
// ---------------------------------------------------------------------------
__global__ __launch_bounds__(256, 1) void critic_kernel(
    const float* __restrict__ acs,
    const float* __restrict__ eW1, const float* __restrict__ eb1,
    const float* __restrict__ eW2, const float* __restrict__ eb2,
    const float* __restrict__ iW1, const float* __restrict__ ib1,
    const float* __restrict__ iW2, const float* __restrict__ ib2,
    float* __restrict__ out, int B)
{
    extern __shared__ float smf[];
    const int tid = threadIdx.x, wid = tid >> 5, lane = tid & 31;
    const int g = lane >> 2, t = lane & 3;
    const int wm = wid >> 1, wn = wid & 1;
    const int wr = wm * 32, wc = wn * 64;
    const int p = blockIdx.y;

    int i, head;
    const float *W1, *b1, *W2, *b2;
    float* outp;
    if (p < A_ * H_) {
        i = p / H_; int j = p % H_; head = j;
        W1 = eW1 + (size_t)(j * A_ + i) * IN_ * D_;
        b1 = eb1 + (size_t)(j * A_ + i) * D_;
        W2 = eW2 + (size_t)(j * A_ + i) * D_ * C_;
        b2 = eb2 + (size_t)(j * A_ + i) * C_;
        outp = out + (size_t)p * B;
    } else {
        int q = p - A_ * H_;
        i = q / HI_; int j = q % HI_; head = j + 1;
        W1 = iW1 + (size_t)(j * A_ + i) * IN_ * D_;
        b1 = ib1 + (size_t)(j * A_ + i) * D_;
        W2 = iW2 + (size_t)(j * A_ + i) * D_ * C_;
        b2 = ib2 + (size_t)(j * A_ + i) * C_;
        outp = out + (size_t)(A_ * H_) * B + (size_t)q * B;
    }
    const float* acsA[3];
    acsA[0] = acs + (size_t)(c_loo[i][0] * H_ + head) * B * C_;
    acsA[1] = acs + (size_t)(c_loo[i][1] * H_ + head) * B * C_;
    acsA[2] = acs + (size_t)(c_loo[i][2] * H_ + head) * B * C_;
    const float* acsSelf = acs + (size_t)(i * H_ + head) * B * C_;

    // ---- stage W1 (cvt.rna), W2 (stride 17), b1, b2 ----
    for (int it = 0; it < 22; it++) {
        int fi = it * 256 + tid;            // 5632 float4
        int k = fi >> 5, n4 = fi & 31;
        float4 v = *(const float4*)(W1 + (size_t)k * D_ + n4 * 4);
        uint4 w; w.x = tf32r(v.x); w.y = tf32r(v.y);
        w.z = tf32r(v.z); w.w = tf32r(v.w);
        *(uint4*)(smf + WS_OFF + k * WS_ST + n4 * 4) = w;
    }
    for (int it = 0; it < 8; it++) {
        int idx = it * 256 + tid;           // 2048 floats
        int d = idx >> 4, c = idx & 15;
        smf[W2_OFF + d * 17 + c] = W2[idx];
    }
    if (tid < D_) smf[B1_OFF + tid] = b1[tid];
    if (tid < C_) smf[B2_OFF + tid] = b2[tid];

    const uint32_t xbase = smem_u32(smf + XS_OFF);
    const int tile0 = blockIdx.x * NT;

    // prologue: stage X tile 0 (128 rows x 44 chunks of 16B)
    {
        int row0 = tile0 * 128;
        for (int it = 0; it < 22; it++) {
            int idx = it * 256 + tid;       // 5632
            int c = idx % 44, row = idx / 44;
            const void* src;
            if (c < 12)
                src = acsA[c >> 2] + (size_t)(row0 + row) * C_ + (c & 3) * 4;
            else
                src = g_enc + (size_t)(row0 + row) * D_ + (c - 12) * 4;
            cpasync16(xbase + (uint32_t)(row * XS_ST + c * 4) * 4, src);
        }
        CPCOMMIT();
    }
    CPWAIT0();
    __syncthreads();

    int* cidx = (int*)(smf + CIDX_OFF);

    for (int tt = 0; tt < NT; tt++) {
        const int row0 = (tile0 + tt) * 128;
        float acc[2][8][4];
#pragma unroll
        for (int mi = 0; mi < 2; mi++)
#pragma unroll
            for (int ni = 0; ni < 8; ni++)
#pragma unroll
                for (int e = 0; e < 4; e++) acc[mi][ni][e] = 0.f;

        const uint32_t* Xu = (const uint32_t*)(smf + XS_OFF);
        const uint32_t* Wu = (const uint32_t*)(smf + WS_OFF);
#pragma unroll
        for (int ks = 0; ks < 22; ks++) {
            const int k0 = ks * 8;
            uint32_t a[2][4], b[8][2];
#pragma unroll
            for (int mi = 0; mi < 2; mi++) {
                int r = wr + mi * 16 + g;
                a[mi][0] = Xu[r * XS_ST + k0 + t];
                a[mi][1] = Xu[(r + 8) * XS_ST + k0 + t];
                a[mi][2] = Xu[r * XS_ST + k0 + t + 4];
                a[mi][3] = Xu[(r + 8) * XS_ST + k0 + t + 4];
            }
#pragma unroll
            for (int ni = 0; ni < 8; ni++) {
                int n = wc + ni * 8 + g;
                b[ni][0] = Wu[(k0 + t) * WS_ST + n];
                b[ni][1] = Wu[(k0 + t + 4) * WS_ST + n];
            }
#pragma unroll
            for (int mi = 0; mi < 2; mi++)
#pragma unroll
                for (int ni = 0; ni < 8; ni++)
                    mma8(acc[mi][ni], a[mi], b[ni]);
        }
        __syncthreads();   // all warps done with Xs

        // restage next tile (async) + argmax for this tile
        if (tt + 1 < NT) {
            int nrow0 = (tile0 + tt + 1) * 128;
            for (int it = 0; it < 22; it++) {
                int idx = it * 256 + tid;
                int c = idx % 44, row = idx / 44;
                const void* src;
                if (c < 12)
                    src = acsA[c >> 2] + (size_t)(nrow0 + row) * C_ + (c & 3) * 4;
                else
                    src = g_enc + (size_t)(nrow0 + row) * D_ + (c - 12) * 4;
                cpasync16(xbase + (uint32_t)(row * XS_ST + c * 4) * 4, src);
            }
            CPCOMMIT();
        }
        if (tid < 128) {
            const float* ar = acsSelf + (size_t)(row0 + tid) * C_;
            float best = ar[0]; int c = 0;
#pragma unroll
            for (int cc = 1; cc < C_; cc++) {
                float v = ar[cc];
                if (v > best) { best = v; c = cc; }
            }
            cidx[tid] = c;
        }
        __syncthreads();   // cidx visible

        // epilogue: relu(acc+b1) dot W2[:,c], reduce over t lanes
        float s[2][2];
#pragma unroll
        for (int mi = 0; mi < 2; mi++) {
            int r0 = wr + mi * 16 + g;
            int cR0 = cidx[r0], cR1 = cidx[r0 + 8];
            float s0 = 0.f, s1 = 0.f;
#pragma unroll
            for (int ni = 0; ni < 8; ni++) {
                int col0 = wc + ni * 8 + 2 * t;
                float bb0 = smf[B1_OFF + col0], bb1 = smf[B1_OFF + col0 + 1];
                float w00 = smf[W2_OFF + col0 * 17 + cR0];
                float w01 = smf[W2_OFF + (col0 + 1) * 17 + cR0];
                float w10 = smf[W2_OFF + col0 * 17 + cR1];
                float w11 = smf[W2_OFF + (col0 + 1) * 17 + cR1];
                s0 += fmaxf(acc[mi][ni][0] + bb0, 0.f) * w00
                    + fmaxf(acc[mi][ni][1] + bb1, 0.f) * w01;
                s1 += fmaxf(acc[mi][ni][2] + bb0, 0.f) * w10
                    + fmaxf(acc[mi][ni][3] + bb1, 0.f) * w11;
            }
            s0 += __shfl_xor_sync(0xffffffffu, s0, 1);
            s0 += __shfl_xor_sync(0xffffffffu, s0, 2);
            s1 += __shfl_xor_sync(0xffffffffu, s1, 1);
            s1 += __shfl_xor_sync(0xffffffffu, s1, 2);
            s[mi][0] = s0; s[mi][1] = s1;
        }
        if (wn == 0 && t == 0) {
#pragma unroll
            for (int mi = 0; mi < 2; mi++) {
                int r0 = wr + mi * 16 + g;
                smf[PART_OFF + r0] = s[mi][0];
                smf[PART_OFF + r0 + 8] = s[mi][1];
            }
        }
        __syncthreads();
        if (wn == 1 && t == 0) {
#pragma unroll
            for (int mi = 0; mi < 2; mi++) {
                int r0 = wr + mi * 16 + g;
                outp[row0 + r0] = s[mi][0] + smf[PART_OFF + r0]
                                + smf[B2_OFF + cidx[r0]];
                outp[row0 + r0 + 8] = s[mi][1] + smf[PART_OFF + r0 + 8]
                                    + smf[B2_OFF + cidx[r0 + 8]];
            }
        }
        if (tt + 1 < NT) CPWAIT0();
        __syncthreads();
    }
}

// ---------------------------------------------------------------------------
extern "C" void kernel_launch(void* const* d_in, const int* in_sizes, int n_in,
                              void* d_out, int out_size)
{
    const float* state = (const float*)d_in[0];
    const float* acs   = (const float*)d_in[1];
    const float* encW  = (const float*)d_in[2];
    const float* encb  = (const float*)d_in[3];
    const float* eW1   = (const float*)d_in[4];
    const float* eb1   = (const float*)d_in[5];
    const float* eW2   = (const float*)d_in[6];
    const float* eb2   = (const float*)d_in[7];
    const float* iW1   = (const float*)d_in[8];
    const float* ib1   = (const float*)d_in[9];
    const float* iW2   = (const float*)d_in[10];
    const float* ib2   = (const float*)d_in[11];
    float* out = (float*)d_out;

    const int B = in_sizes[0] / S_;          // 32768

    static int inited = 0;
    if (!inited) {
        cudaFuncSetAttribute(enc_kernel,
            cudaFuncAttributeMaxDynamicSharedMemorySize, E_SMEMB);
        cudaFuncSetAttribute(critic_kernel,
            cudaFuncAttributeMaxDynamicSharedMemorySize, K_SMEMB);
        inited = 1;
    }

    enc_kernel<<<B / 64 / NTE, 256, E_SMEMB>>>(state, encW, encb, B);

    dim3 grid(B / 128 / NT, NPAIR);
    critic_kernel<<<grid, 256, K_SMEMB>>>(acs, eW1, eb1, eW2, eb2,
                                          iW1, ib1, iW2, ib2, out, B);
}